// round 2
// baseline (speedup 1.0000x reference)
#include <cuda_runtime.h>
#include <cstdint>

#define EDIM 512
#define JDIM 1536
#define TLEN 256
#define NBLK 32      // blocks per sentence in the scan
#define POOL 128

// ---------------- scratch layout (floats) ----------------
#define OFF_XA   0
#define OFF_XB   (OFF_XA + 2*TLEN*EDIM)
#define OFF_GI   (OFF_XB + 2*TLEN*EDIM)
#define OFF_HBUF (OFF_GI + 2*TLEN*JDIM)          // [parity][sentence][EDIM]
#define OFF_FIN  (OFF_HBUF + 2*2*EDIM)           // finals epoch0: [s][l][EDIM]
#define OFF_X2A  (OFF_FIN + 2*2*EDIM)
#define OFF_X2B  (OFF_X2A + 2*2*EDIM)
#define OFF_FIN2 (OFF_X2B + 2*2*EDIM)            // finals epoch1: [s][l][EDIM]
#define OFF_SEQ  (OFF_FIN2 + 2*2*EDIM)           // [s][l][POOL]
#define OFF_GI2  (OFF_SEQ + 2*2*POOL)            // [s][t][JDIM]
#define OFF_HT2  (OFF_GI2 + 2*2*JDIM)            // [s][EDIM]
#define SCRATCH_SZ (OFF_HT2 + 2*EDIM)

__device__ float    d_scratch[SCRATCH_SZ];
__device__ unsigned g_bar_count[2];
__device__ unsigned g_bar_gen[2];

__device__ __forceinline__ float sigf(float x) { return 1.f / (1.f + __expf(-x)); }

// Sense/generation barrier among the NBLK blocks of one sentence.
// All threads fence their own global stores before syncthreads; thread 0
// arrives; last arriver resets count (guarded by gen bump behind a fence).
__device__ __forceinline__ void sent_barrier(int s, unsigned &gen) {
    __threadfence();
    __syncthreads();
    if (threadIdx.x == 0) {
        unsigned a = atomicAdd(&g_bar_count[s], 1u);
        if (a == (unsigned)(NBLK - 1)) {
            g_bar_count[s] = 0u;
            __threadfence();
            atomicAdd(&g_bar_gen[s], 1u);
        } else {
            while (*(volatile unsigned*)&g_bar_gen[s] == gen) { }
            __threadfence();
        }
    }
    gen++;
    __syncthreads();
}

// ---------------- embedding gather ----------------
__global__ void embed_kernel(float* __restrict__ x, const int* __restrict__ sA,
                             const int* __restrict__ sB, const float* __restrict__ emb) {
    const int t = blockIdx.x, s = blockIdx.y;
    const int idx = (s == 0) ? sA[t] : sB[t];
    const float4* src = reinterpret_cast<const float4*>(emb + (size_t)idx * EDIM);
    float4* dst = reinterpret_cast<float4*>(x + ((size_t)s * TLEN + t) * EDIM);
    dst[threadIdx.x] = src[threadIdx.x];   // 128 threads * 16B = 2KB
}

// ---------------- gi = X @ W^T + b  (tiled, L up to 256) ----------------
// X: [2][L][512]  W: [1536][512]  out: [2][L][1536]
__global__ void __launch_bounds__(256) gemm_gi_kernel(
    float* __restrict__ gi, const float* __restrict__ X,
    const float* __restrict__ W, const float* __restrict__ bias, int L) {
    const int s  = blockIdx.z;
    const int t0 = blockIdx.y * 64;
    const int j0 = blockIdx.x * 64;
    __shared__ float xs[16][68];
    __shared__ float ws[16][68];
    const int tid = threadIdx.x;
    const int tx = tid & 15, ty = tid >> 4;
    float acc[4][4];
#pragma unroll
    for (int i = 0; i < 4; i++)
#pragma unroll
        for (int q = 0; q < 4; q++) acc[i][q] = 0.f;

    const float* Xs = X + (size_t)s * L * EDIM;
    for (int k0 = 0; k0 < EDIM; k0 += 16) {
#pragma unroll
        for (int i = 0; i < 4; i++) {
            const int r = ty + 16 * i;        // 0..63
            const int t = t0 + r;
            xs[tx][r] = (t < L) ? Xs[(size_t)t * EDIM + k0 + tx] : 0.f;
            ws[tx][r] = W[(size_t)(j0 + r) * EDIM + k0 + tx];
        }
        __syncthreads();
#pragma unroll
        for (int kk = 0; kk < 16; kk++) {
            float a[4], bb[4];
#pragma unroll
            for (int i = 0; i < 4; i++) { a[i] = xs[kk][ty * 4 + i]; bb[i] = ws[kk][tx * 4 + i]; }
#pragma unroll
            for (int i = 0; i < 4; i++)
#pragma unroll
                for (int q = 0; q < 4; q++) acc[i][q] += a[i] * bb[q];
        }
        __syncthreads();
    }
#pragma unroll
    for (int i = 0; i < 4; i++) {
        const int t = t0 + ty * 4 + i;
        if (t < L) {
#pragma unroll
            for (int q = 0; q < 4; q++) {
                const int j = j0 + tx * 4 + q;
                gi[((size_t)s * L + t) * JDIM + j] = acc[i][q] + bias[j];
            }
        }
    }
}

// ---------------- gi for L==2 sequences (epoch-1 layers) ----------------
__global__ void gi_small_kernel(float* __restrict__ gi, const float* __restrict__ X,
                                const float* __restrict__ W, const float* __restrict__ bias) {
    const int s = blockIdx.y;
    const int j = blockIdx.x * 256 + threadIdx.x;   // [0,1536)
    __shared__ float sx[2 * EDIM];
    for (int i = threadIdx.x; i < 2 * EDIM; i += 256) sx[i] = X[(size_t)s * 2 * EDIM + i];
    __syncthreads();
    const float* wr = W + (size_t)j * EDIM;
    float a0 = bias[j], a1 = a0;
#pragma unroll 4
    for (int k = 0; k < EDIM; k += 4) {
        const float4 w4 = *reinterpret_cast<const float4*>(wr + k);
        a0 += w4.x * sx[k] + w4.y * sx[k + 1] + w4.z * sx[k + 2] + w4.w * sx[k + 3];
        a1 += w4.x * sx[EDIM + k] + w4.y * sx[EDIM + k + 1] + w4.z * sx[EDIM + k + 2] + w4.w * sx[EDIM + k + 3];
    }
    gi[((size_t)s * 2 + 0) * JDIM + j] = a0;
    gi[((size_t)s * 2 + 1) * JDIM + j] = a1;
}

// ---------------- multi-block GRU scan ----------------
// grid (NBLK, 2). Block b owns h-elements [b*16, b*16+16) -> 48 Whh rows (96KB, L1-resident).
// Thread t: e = t>>4 (element within block), kc = t&15 (k-chunk lane).
// h ping-pongs between two L2 buffers indexed by step parity (no read/write race).
__global__ void __launch_bounds__(256) scan_kernel(
    float* __restrict__ x_out, float* __restrict__ hT, int hT_stride,
    const float* __restrict__ gi, const float* __restrict__ Whh,
    const float* __restrict__ bhh, int L) {
    const int s = blockIdx.y;
    const int b = blockIdx.x;
    const int tid = threadIdx.x;
    const int e = tid >> 4, kc = tid & 15;
    const int elem = b * 16 + e;
    float* hbuf = d_scratch + OFF_HBUF;

    __shared__ float sh[EDIM];
    __shared__ unsigned sgen;
    if (tid == 0) sgen = *(volatile unsigned*)&g_bar_gen[s];
    if (tid < 16) __stcg(&hbuf[(0 * 2 + s) * EDIM + b * 16 + tid], 0.f);
    __syncthreads();
    unsigned gen = sgen;
    sent_barrier(s, gen);                 // zeros visible everywhere

    const float4* Wr = reinterpret_cast<const float4*>(Whh + (size_t)elem * EDIM);
    const float4* Wz = reinterpret_cast<const float4*>(Whh + (size_t)(EDIM + elem) * EDIM);
    const float4* Wn = reinterpret_cast<const float4*>(Whh + (size_t)(2 * EDIM + elem) * EDIM);
    const float bhr = bhh[elem], bhz = bhh[EDIM + elem], bhn = bhh[2 * EDIM + elem];

    for (int step = 0; step < L; step++) {
        const int par = step & 1;
        const float* hin = hbuf + (par * 2 + s) * EDIM;
        float* hout = hbuf + ((par ^ 1) * 2 + s) * EDIM;
        sh[tid]       = __ldcg(hin + tid);
        sh[tid + 256] = __ldcg(hin + tid + 256);
        __syncthreads();

        float pr = 0.f, pz = 0.f, pn = 0.f;
        const float4* sh4 = reinterpret_cast<const float4*>(sh);
#pragma unroll
        for (int u = 0; u < 8; u++) {
            const int k4 = kc + u * 16;   // float4 index; 16 lanes -> 256B contiguous
            const float4 h4 = sh4[k4];
            float4 w;
            w = Wr[k4]; pr += w.x * h4.x; pr += w.y * h4.y; pr += w.z * h4.z; pr += w.w * h4.w;
            w = Wz[k4]; pz += w.x * h4.x; pz += w.y * h4.y; pz += w.z * h4.z; pz += w.w * h4.w;
            w = Wn[k4]; pn += w.x * h4.x; pn += w.y * h4.y; pn += w.z * h4.z; pn += w.w * h4.w;
        }
#pragma unroll
        for (int off = 8; off > 0; off >>= 1) {
            pr += __shfl_down_sync(0xffffffffu, pr, off, 16);
            pz += __shfl_down_sync(0xffffffffu, pz, off, 16);
            pn += __shfl_down_sync(0xffffffffu, pn, off, 16);
        }
        if (kc == 0) {
            const float* git = gi + (size_t)(s * L + step) * JDIM;
            const float r = sigf(git[elem] + pr + bhr);
            const float z = sigf(git[EDIM + elem] + pz + bhz);
            const float n = tanhf(git[2 * EDIM + elem] + r * (pn + bhn));
            const float hnew = (1.f - z) * n + z * sh[elem];
            __stcg(hout + elem, hnew);
            x_out[(size_t)(s * L + step) * EDIM + elem] = hnew;
            if (step == L - 1) hT[s * hT_stride + elem] = hnew;
        }
        sent_barrier(s, gen);
    }
}

// ---------------- conv1d(stride2,pad255) + bias + global maxpool ----------------
// in: finals2 [s][ch=2][512], w: [oc=2][ic=2][512], out seq[s][oc][q]=rowmax (window covers all)
__global__ void conv_pool_kernel(float* __restrict__ seq, const float* __restrict__ hin,
                                 const float* __restrict__ cw, const float* __restrict__ cb) {
    const int s = blockIdx.x >> 1, oc = blockIdx.x & 1;
    __shared__ float sin[2 * EDIM];
    __shared__ float sw[2 * EDIM];
    __shared__ float red[256];
    const int tid = threadIdx.x;
    for (int i = tid; i < 2 * EDIM; i += 256) {
        sin[i] = hin[(size_t)s * 2 * EDIM + i];
        sw[i]  = cw[(size_t)oc * 2 * EDIM + i];
    }
    __syncthreads();
    float v = cb[oc];
    const int base = 2 * tid - 255;        // p = tid in [0,256)
    for (int k = 0; k < EDIM; k++) {
        const int pos = base + k;
        if (pos >= 0 && pos < EDIM)
            v += sw[k] * sin[pos] + sw[EDIM + k] * sin[EDIM + pos];
    }
    red[tid] = v;
    __syncthreads();
    for (int off = 128; off > 0; off >>= 1) {
        if (tid < off) red[tid] = fmaxf(red[tid], red[tid + off]);
        __syncthreads();
    }
    const float M = red[0];
    if (tid < POOL) seq[((size_t)s * 2 + oc) * POOL + tid] = M;
}

// ---------------- gi2 = seq @ Wih2^T + bih2 (K=128, L=2) ----------------
__global__ void gi2_kernel(float* __restrict__ gi2, const float* __restrict__ seq,
                           const float* __restrict__ W2, const float* __restrict__ b2) {
    const int j = blockIdx.x * 256 + threadIdx.x;  // [0,1536)
    const int t = blockIdx.y, s = blockIdx.z;
    __shared__ float ss[POOL];
    if (threadIdx.x < POOL) ss[threadIdx.x] = seq[((size_t)s * 2 + t) * POOL + threadIdx.x];
    __syncthreads();
    const float* wr = W2 + (size_t)j * POOL;
    float acc = b2[j];
#pragma unroll 4
    for (int q = 0; q < POOL; q += 4) {
        const float4 w4 = *reinterpret_cast<const float4*>(wr + q);
        acc += w4.x * ss[q] + w4.y * ss[q + 1] + w4.z * ss[q + 2] + w4.w * ss[q + 3];
    }
    gi2[((size_t)s * 2 + t) * JDIM + j] = acc;
}

// ---------------- head: Double_Linear + tanh + linear + sigmoid ----------------
__global__ void head_kernel(float* __restrict__ out, const float* __restrict__ hT2,
                            const float* __restrict__ WA, const float* __restrict__ WB,
                            const float* __restrict__ b_bi, const float* __restrict__ Wlin,
                            const float* __restrict__ blin) {
    const int j = threadIdx.x;   // 256 = TEMP
    __shared__ float shx[EDIM];
    __shared__ float shv[EDIM];
    __shared__ float red[256];
    for (int k = j; k < EDIM; k += 256) {
        const float a = hT2[k], b = hT2[EDIM + k];
        shx[k] = a * b;
        shv[k] = fabsf(a - b);
    }
    __syncthreads();
    float acc = b_bi[j];
    for (int k = 0; k < EDIM; k++)
        acc += shx[k] * WA[(size_t)k * 256 + j] + shv[k] * WB[(size_t)k * 256 + j];
    const float ht = tanhf(acc);
    red[j] = ht * Wlin[j];
    __syncthreads();
    for (int off = 128; off > 0; off >>= 1) {
        if (j < off) red[j] += red[j + off];
        __syncthreads();
    }
    if (j == 0) out[0] = 1.f / (1.f + __expf(-(red[0] + blin[0])));
}

// ---------------- launch ----------------
extern "C" void kernel_launch(void* const* d_in, const int* in_sizes, int n_in,
                              void* d_out, int out_size) {
    const int*   sentA  = (const int*)  d_in[0];
    const int*   sentB  = (const int*)  d_in[1];
    const float* emb    = (const float*)d_in[2];
    const float* Wih1   = (const float*)d_in[3];   // [2][1536][512]
    const float* Whh1   = (const float*)d_in[4];   // [2][1536][512]
    const float* bih1   = (const float*)d_in[5];   // [2][1536]
    const float* bhh1   = (const float*)d_in[6];   // [2][1536]
    const float* conv_w = (const float*)d_in[7];   // [2][2][512]
    const float* conv_b = (const float*)d_in[8];   // [2]
    const float* Wih2   = (const float*)d_in[9];   // [1536][128]
    const float* Whh2   = (const float*)d_in[10];  // [1536][512]
    const float* bih2   = (const float*)d_in[11];  // [1536]
    const float* bhh2   = (const float*)d_in[12];  // [1536]
    const float* WA     = (const float*)d_in[13];  // [512][256]
    const float* WB     = (const float*)d_in[14];  // [512][256]
    const float* b_bi   = (const float*)d_in[15];  // [256]
    const float* W_lin  = (const float*)d_in[16];  // [1][256]
    const float* b_lin  = (const float*)d_in[17];  // [1]
    float* out = (float*)d_out;

    float* S = nullptr;
    cudaGetSymbolAddress((void**)&S, d_scratch);

    float* xA   = S + OFF_XA;
    float* xB   = S + OFF_XB;
    float* gi   = S + OFF_GI;
    float* fin  = S + OFF_FIN;
    float* x2a  = S + OFF_X2A;
    float* x2b  = S + OFF_X2B;
    float* fin2 = S + OFF_FIN2;
    float* seq  = S + OFF_SEQ;
    float* gi2  = S + OFF_GI2;
    float* hT2  = S + OFF_HT2;

    const size_t WSTRIDE = (size_t)JDIM * EDIM;

    // embedding
    embed_kernel<<<dim3(TLEN, 2), 128>>>(xA, sentA, sentB, emb);

    // ---- epoch 0 (L = 256) ----
    gemm_gi_kernel<<<dim3(JDIM / 64, TLEN / 64, 2), 256>>>(gi, xA, Wih1, bih1, TLEN);
    scan_kernel<<<dim3(NBLK, 2), 256>>>(xB, fin + 0 * EDIM, 2 * EDIM, gi, Whh1, bhh1, TLEN);

    gemm_gi_kernel<<<dim3(JDIM / 64, TLEN / 64, 2), 256>>>(gi, xB, Wih1 + WSTRIDE, bih1 + JDIM, TLEN);
    scan_kernel<<<dim3(NBLK, 2), 256>>>(xA, fin + 1 * EDIM, 2 * EDIM, gi, Whh1 + WSTRIDE, bhh1 + JDIM, TLEN);

    // ---- epoch 1 (L = 2, input = stacked finals) ----
    gi_small_kernel<<<dim3(JDIM / 256, 2), 256>>>(gi, fin, Wih1, bih1);
    scan_kernel<<<dim3(NBLK, 2), 256>>>(x2a, fin2 + 0 * EDIM, 2 * EDIM, gi, Whh1, bhh1, 2);

    gi_small_kernel<<<dim3(JDIM / 256, 2), 256>>>(gi, x2a, Wih1 + WSTRIDE, bih1 + JDIM);
    scan_kernel<<<dim3(NBLK, 2), 256>>>(x2b, fin2 + 1 * EDIM, 2 * EDIM, gi, Whh1 + WSTRIDE, bhh1 + JDIM, 2);

    // conv + pool
    conv_pool_kernel<<<4, 256>>>(seq, fin2, conv_w, conv_b);

    // rnn_second (L = 2)
    gi2_kernel<<<dim3(JDIM / 256, 2, 2), 256>>>(gi2, seq, Wih2, bih2);
    scan_kernel<<<dim3(NBLK, 2), 256>>>(x2a, hT2, EDIM, gi2, Whh2, bhh2, 2);

    // head
    head_kernel<<<1, 256>>>(out, hT2, WA, WB, b_bi, W_lin, b_lin);
}

// round 3
// speedup vs baseline: 1.5226x; 1.5226x over previous
#include <cuda_runtime.h>
#include <cstdint>

#define EDIM 512
#define JDIM 1536
#define TLEN 256
#define NBLK 32      // blocks per sentence in the scan
#define POOL 128

// ---------------- scratch layout (floats) ----------------
#define OFF_XA   0
#define OFF_XB   (OFF_XA + 2*TLEN*EDIM)
#define OFF_GI   (OFF_XB + 2*TLEN*EDIM)
#define OFF_HBUF (OFF_GI + 2*TLEN*JDIM)          // [parity][sentence][EDIM]
#define OFF_FIN  (OFF_HBUF + 2*2*EDIM)           // finals epoch0: [s][l][EDIM]
#define OFF_X2A  (OFF_FIN + 2*2*EDIM)
#define OFF_X2B  (OFF_X2A + 2*2*EDIM)
#define OFF_FIN2 (OFF_X2B + 2*2*EDIM)            // finals epoch1: [s][l][EDIM]
#define OFF_SEQ  (OFF_FIN2 + 2*2*EDIM)           // [s][l][POOL]
#define OFF_GI2  (OFF_SEQ + 2*2*POOL)            // [s][t][JDIM]
#define OFF_HT2  (OFF_GI2 + 2*2*JDIM)            // [s][EDIM]
#define SCRATCH_SZ (OFF_HT2 + 2*EDIM)

__device__ float d_scratch[SCRATCH_SZ];
// per-block completion flags: [sentence][block], one 128B line per sentence
__device__ __align__(128) unsigned g_flags[2 * NBLK];

__device__ __forceinline__ float sigf(float x) { return 1.f / (1.f + __expf(-x)); }

__device__ __forceinline__ void flag_release(unsigned* p, unsigned v) {
    asm volatile("fence.acq_rel.gpu;" ::: "memory");
    asm volatile("st.relaxed.gpu.global.u32 [%0], %1;" :: "l"(p), "r"(v) : "memory");
}
__device__ __forceinline__ unsigned flag_acquire(const unsigned* p) {
    unsigned v;
    asm volatile("ld.acquire.gpu.global.u32 %0, [%1];" : "=r"(v) : "l"(p) : "memory");
    return v;
}

// ---------------- embedding gather (also zeroes scan flags each replay) ----------------
__global__ void embed_kernel(float* __restrict__ x, const int* __restrict__ sA,
                             const int* __restrict__ sB, const float* __restrict__ emb) {
    const int t = blockIdx.x, s = blockIdx.y;
    if (t == 0 && s == 0 && threadIdx.x < 2 * NBLK) g_flags[threadIdx.x] = 0u;
    const int idx = (s == 0) ? sA[t] : sB[t];
    const float4* src = reinterpret_cast<const float4*>(emb + (size_t)idx * EDIM);
    float4* dst = reinterpret_cast<float4*>(x + ((size_t)s * TLEN + t) * EDIM);
    dst[threadIdx.x] = src[threadIdx.x];   // 128 threads * 16B = 2KB
}

// ---------------- gi = X @ W^T + b  (tiled, L up to 256) ----------------
__global__ void __launch_bounds__(256) gemm_gi_kernel(
    float* __restrict__ gi, const float* __restrict__ X,
    const float* __restrict__ W, const float* __restrict__ bias, int L) {
    const int s  = blockIdx.z;
    const int t0 = blockIdx.y * 64;
    const int j0 = blockIdx.x * 64;
    __shared__ float xs[16][68];
    __shared__ float ws[16][68];
    const int tid = threadIdx.x;
    const int tx = tid & 15, ty = tid >> 4;
    float acc[4][4];
#pragma unroll
    for (int i = 0; i < 4; i++)
#pragma unroll
        for (int q = 0; q < 4; q++) acc[i][q] = 0.f;

    const float* Xs = X + (size_t)s * L * EDIM;
    for (int k0 = 0; k0 < EDIM; k0 += 16) {
#pragma unroll
        for (int i = 0; i < 4; i++) {
            const int r = ty + 16 * i;        // 0..63
            const int t = t0 + r;
            xs[tx][r] = (t < L) ? Xs[(size_t)t * EDIM + k0 + tx] : 0.f;
            ws[tx][r] = W[(size_t)(j0 + r) * EDIM + k0 + tx];
        }
        __syncthreads();
#pragma unroll
        for (int kk = 0; kk < 16; kk++) {
            float a[4], bb[4];
#pragma unroll
            for (int i = 0; i < 4; i++) { a[i] = xs[kk][ty * 4 + i]; bb[i] = ws[kk][tx * 4 + i]; }
#pragma unroll
            for (int i = 0; i < 4; i++)
#pragma unroll
                for (int q = 0; q < 4; q++) acc[i][q] += a[i] * bb[q];
        }
        __syncthreads();
    }
#pragma unroll
    for (int i = 0; i < 4; i++) {
        const int t = t0 + ty * 4 + i;
        if (t < L) {
#pragma unroll
            for (int q = 0; q < 4; q++) {
                const int j = j0 + tx * 4 + q;
                gi[((size_t)s * L + t) * JDIM + j] = acc[i][q] + bias[j];
            }
        }
    }
}

// ---------------- gi for L==2 sequences (epoch-1 layers) ----------------
__global__ void gi_small_kernel(float* __restrict__ gi, const float* __restrict__ X,
                                const float* __restrict__ W, const float* __restrict__ bias) {
    const int s = blockIdx.y;
    const int j = blockIdx.x * 256 + threadIdx.x;   // [0,1536)
    __shared__ float sx[2 * EDIM];
    for (int i = threadIdx.x; i < 2 * EDIM; i += 256) sx[i] = X[(size_t)s * 2 * EDIM + i];
    __syncthreads();
    const float* wr = W + (size_t)j * EDIM;
    float a0 = bias[j], a1 = a0;
#pragma unroll 4
    for (int k = 0; k < EDIM; k += 4) {
        const float4 w4 = *reinterpret_cast<const float4*>(wr + k);
        a0 += w4.x * sx[k] + w4.y * sx[k + 1] + w4.z * sx[k + 2] + w4.w * sx[k + 3];
        a1 += w4.x * sx[EDIM + k] + w4.y * sx[EDIM + k + 1] + w4.z * sx[EDIM + k + 2] + w4.w * sx[EDIM + k + 3];
    }
    gi[((size_t)s * 2 + 0) * JDIM + j] = a0;
    gi[((size_t)s * 2 + 1) * JDIM + j] = a1;
}

// ---------------- multi-block GRU scan (register weights, flag sync) ----------------
// grid (NBLK, 2). Block b owns h-elements [b*16, b*16+16).
// Thread (e = tid>>4, kc = tid&15): rows {elem, elem+512, elem+1024}, k in [kc*32, kc*32+32).
// 96 weight floats live in registers for the whole scan.
// h ping-pongs between two L2 buffers by step parity; sync is per-block
// release/acquire completion counters (flag = base + #writes completed).
__global__ void __launch_bounds__(256, 1) scan_kernel(
    float* __restrict__ x_out, float* __restrict__ hT, int hT_stride,
    const float* __restrict__ gi, const float* __restrict__ Whh,
    const float* __restrict__ bhh, int L, unsigned base) {
    const int s = blockIdx.y;
    const int b = blockIdx.x;
    const int tid = threadIdx.x;
    const int e = tid >> 4, kc = tid & 15;
    const int elem = b * 16 + e;
    float* hbuf = d_scratch + OFF_HBUF;
    unsigned* myflag = &g_flags[s * NBLK + b];

    // ---- weights -> registers ----
    float4 wr[8], wz[8], wn[8];
    {
        const float4* Rr = reinterpret_cast<const float4*>(Whh + (size_t)elem * EDIM) + kc * 8;
        const float4* Rz = reinterpret_cast<const float4*>(Whh + (size_t)(EDIM + elem) * EDIM) + kc * 8;
        const float4* Rn = reinterpret_cast<const float4*>(Whh + (size_t)(2 * EDIM + elem) * EDIM) + kc * 8;
#pragma unroll
        for (int u = 0; u < 8; u++) { wr[u] = Rr[u]; wz[u] = Rz[u]; wn[u] = Rn[u]; }
    }
    const float bhr = bhh[elem], bhz = bhh[EDIM + elem], bhn = bhh[2 * EDIM + elem];

    __shared__ float sh[EDIM];

    // ---- initial h = 0 into parity-0 buffer ----
    if (tid < 16) __stcg(&hbuf[(0 * 2 + s) * EDIM + b * 16 + tid], 0.f);
    __syncthreads();
    if (tid == 0) flag_release(myflag, base + 1);

    for (int step = 0; step < L; step++) {
        const unsigned target = base + (unsigned)step + 1u;
        if (tid < NBLK) {
            const unsigned* fp = &g_flags[s * NBLK + tid];
            while (flag_acquire(fp) < target) { }
        }
        __syncthreads();

        const int par = step & 1;
        const float* hin = hbuf + (par * 2 + s) * EDIM;
        float* hout = hbuf + ((par ^ 1) * 2 + s) * EDIM;

        // stage h into smem with XOR swizzle (conflict-degree 2 on read)
        if (tid < 128) {
            const float4 v = __ldcg(reinterpret_cast<const float4*>(hin) + tid);
            const int slot = (tid & ~7) | ((tid & 7) ^ ((tid >> 3) & 7));
            reinterpret_cast<float4*>(sh)[slot] = v;
        }
        __syncthreads();

        float pr = 0.f, pz = 0.f, pn = 0.f;
#pragma unroll
        for (int u = 0; u < 8; u++) {
            const int slot = kc * 8 + (u ^ (kc & 7));
            const float4 h4 = reinterpret_cast<const float4*>(sh)[slot];
            pr += wr[u].x * h4.x; pr += wr[u].y * h4.y; pr += wr[u].z * h4.z; pr += wr[u].w * h4.w;
            pz += wz[u].x * h4.x; pz += wz[u].y * h4.y; pz += wz[u].z * h4.z; pz += wz[u].w * h4.w;
            pn += wn[u].x * h4.x; pn += wn[u].y * h4.y; pn += wn[u].z * h4.z; pn += wn[u].w * h4.w;
        }
#pragma unroll
        for (int off = 8; off > 0; off >>= 1) {
            pr += __shfl_down_sync(0xffffffffu, pr, off, 16);
            pz += __shfl_down_sync(0xffffffffu, pz, off, 16);
            pn += __shfl_down_sync(0xffffffffu, pn, off, 16);
        }
        if (kc == 0) {
            // old h[elem] from swizzled smem
            const int k4o = elem >> 2;
            const int sloto = (k4o & ~7) | ((k4o & 7) ^ ((k4o >> 3) & 7));
            const float hold = sh[sloto * 4 + (elem & 3)];
            const float* git = gi + (size_t)(s * L + step) * JDIM;
            const float r = sigf(git[elem] + pr + bhr);
            const float z = sigf(git[EDIM + elem] + pz + bhz);
            const float n = tanhf(git[2 * EDIM + elem] + r * (pn + bhn));
            const float hnew = (1.f - z) * n + z * hold;
            __stcg(hout + elem, hnew);
            x_out[(size_t)(s * L + step) * EDIM + elem] = hnew;
            if (step == L - 1) hT[s * hT_stride + elem] = hnew;
        }
        __syncthreads();
        if (tid == 0) flag_release(myflag, base + (unsigned)step + 2u);
    }
}

// ---------------- conv1d(stride2,pad255) + bias + global maxpool ----------------
__global__ void conv_pool_kernel(float* __restrict__ seq, const float* __restrict__ hin,
                                 const float* __restrict__ cw, const float* __restrict__ cb) {
    const int s = blockIdx.x >> 1, oc = blockIdx.x & 1;
    __shared__ float sin[2 * EDIM];
    __shared__ float sw[2 * EDIM];
    __shared__ float red[256];
    const int tid = threadIdx.x;
    for (int i = tid; i < 2 * EDIM; i += 256) {
        sin[i] = hin[(size_t)s * 2 * EDIM + i];
        sw[i]  = cw[(size_t)oc * 2 * EDIM + i];
    }
    __syncthreads();
    float v = cb[oc];
    const int base = 2 * tid - 255;        // p = tid in [0,256)
    for (int k = 0; k < EDIM; k++) {
        const int pos = base + k;
        if (pos >= 0 && pos < EDIM)
            v += sw[k] * sin[pos] + sw[EDIM + k] * sin[EDIM + pos];
    }
    red[tid] = v;
    __syncthreads();
    for (int off = 128; off > 0; off >>= 1) {
        if (tid < off) red[tid] = fmaxf(red[tid], red[tid + off]);
        __syncthreads();
    }
    const float M = red[0];
    if (tid < POOL) seq[((size_t)s * 2 + oc) * POOL + tid] = M;
}

// ---------------- gi2 = seq @ Wih2^T + bih2 (K=128, L=2) ----------------
__global__ void gi2_kernel(float* __restrict__ gi2, const float* __restrict__ seq,
                           const float* __restrict__ W2, const float* __restrict__ b2) {
    const int j = blockIdx.x * 256 + threadIdx.x;  // [0,1536)
    const int t = blockIdx.y, s = blockIdx.z;
    __shared__ float ss[POOL];
    if (threadIdx.x < POOL) ss[threadIdx.x] = seq[((size_t)s * 2 + t) * POOL + threadIdx.x];
    __syncthreads();
    const float* wr = W2 + (size_t)j * POOL;
    float acc = b2[j];
#pragma unroll 4
    for (int q = 0; q < POOL; q += 4) {
        const float4 w4 = *reinterpret_cast<const float4*>(wr + q);
        acc += w4.x * ss[q] + w4.y * ss[q + 1] + w4.z * ss[q + 2] + w4.w * ss[q + 3];
    }
    gi2[((size_t)s * 2 + t) * JDIM + j] = acc;
}

// ---------------- head: Double_Linear + tanh + linear + sigmoid ----------------
__global__ void head_kernel(float* __restrict__ out, const float* __restrict__ hT2,
                            const float* __restrict__ WA, const float* __restrict__ WB,
                            const float* __restrict__ b_bi, const float* __restrict__ Wlin,
                            const float* __restrict__ blin) {
    const int j = threadIdx.x;   // 256 = TEMP
    __shared__ float shx[EDIM];
    __shared__ float shv[EDIM];
    __shared__ float red[256];
    for (int k = j; k < EDIM; k += 256) {
        const float a = hT2[k], b = hT2[EDIM + k];
        shx[k] = a * b;
        shv[k] = fabsf(a - b);
    }
    __syncthreads();
    float acc = b_bi[j];
    for (int k = 0; k < EDIM; k++)
        acc += shx[k] * WA[(size_t)k * 256 + j] + shv[k] * WB[(size_t)k * 256 + j];
    const float ht = tanhf(acc);
    red[j] = ht * Wlin[j];
    __syncthreads();
    for (int off = 128; off > 0; off >>= 1) {
        if (j < off) red[j] += red[j + off];
        __syncthreads();
    }
    if (j == 0) out[0] = 1.f / (1.f + __expf(-(red[0] + blin[0])));
}

// ---------------- launch ----------------
extern "C" void kernel_launch(void* const* d_in, const int* in_sizes, int n_in,
                              void* d_out, int out_size) {
    const int*   sentA  = (const int*)  d_in[0];
    const int*   sentB  = (const int*)  d_in[1];
    const float* emb    = (const float*)d_in[2];
    const float* Wih1   = (const float*)d_in[3];   // [2][1536][512]
    const float* Whh1   = (const float*)d_in[4];   // [2][1536][512]
    const float* bih1   = (const float*)d_in[5];   // [2][1536]
    const float* bhh1   = (const float*)d_in[6];   // [2][1536]
    const float* conv_w = (const float*)d_in[7];   // [2][2][512]
    const float* conv_b = (const float*)d_in[8];   // [2]
    const float* Wih2   = (const float*)d_in[9];   // [1536][128]
    const float* Whh2   = (const float*)d_in[10];  // [1536][512]
    const float* bih2   = (const float*)d_in[11];  // [1536]
    const float* bhh2   = (const float*)d_in[12];  // [1536]
    const float* WA     = (const float*)d_in[13];  // [512][256]
    const float* WB     = (const float*)d_in[14];  // [512][256]
    const float* b_bi   = (const float*)d_in[15];  // [256]
    const float* W_lin  = (const float*)d_in[16];  // [1][256]
    const float* b_lin  = (const float*)d_in[17];  // [1]
    float* out = (float*)d_out;

    float* S = nullptr;
    cudaGetSymbolAddress((void**)&S, d_scratch);

    float* xA   = S + OFF_XA;
    float* xB   = S + OFF_XB;
    float* gi   = S + OFF_GI;
    float* fin  = S + OFF_FIN;
    float* x2a  = S + OFF_X2A;
    float* x2b  = S + OFF_X2B;
    float* fin2 = S + OFF_FIN2;
    float* seq  = S + OFF_SEQ;
    float* gi2  = S + OFF_GI2;
    float* hT2  = S + OFF_HT2;

    const size_t WSTRIDE = (size_t)JDIM * EDIM;
    const unsigned FB = 512;   // flag base stride per scan launch

    // embedding (also zeroes flags at the start of every replay)
    embed_kernel<<<dim3(TLEN, 2), 128>>>(xA, sentA, sentB, emb);

    // ---- epoch 0 (L = 256) ----
    gemm_gi_kernel<<<dim3(JDIM / 64, TLEN / 64, 2), 256>>>(gi, xA, Wih1, bih1, TLEN);
    scan_kernel<<<dim3(NBLK, 2), 256>>>(xB, fin + 0 * EDIM, 2 * EDIM, gi, Whh1, bhh1, TLEN, 0 * FB);

    gemm_gi_kernel<<<dim3(JDIM / 64, TLEN / 64, 2), 256>>>(gi, xB, Wih1 + WSTRIDE, bih1 + JDIM, TLEN);
    scan_kernel<<<dim3(NBLK, 2), 256>>>(xA, fin + 1 * EDIM, 2 * EDIM, gi, Whh1 + WSTRIDE, bhh1 + JDIM, TLEN, 1 * FB);

    // ---- epoch 1 (L = 2, input = stacked finals) ----
    gi_small_kernel<<<dim3(JDIM / 256, 2), 256>>>(gi, fin, Wih1, bih1);
    scan_kernel<<<dim3(NBLK, 2), 256>>>(x2a, fin2 + 0 * EDIM, 2 * EDIM, gi, Whh1, bhh1, 2, 2 * FB);

    gi_small_kernel<<<dim3(JDIM / 256, 2), 256>>>(gi, x2a, Wih1 + WSTRIDE, bih1 + JDIM);
    scan_kernel<<<dim3(NBLK, 2), 256>>>(x2b, fin2 + 1 * EDIM, 2 * EDIM, gi, Whh1 + WSTRIDE, bhh1 + JDIM, 2, 3 * FB);

    // conv + pool
    conv_pool_kernel<<<4, 256>>>(seq, fin2, conv_w, conv_b);

    // rnn_second (L = 2)
    gi2_kernel<<<dim3(JDIM / 256, 2, 2), 256>>>(gi2, seq, Wih2, bih2);
    scan_kernel<<<dim3(NBLK, 2), 256>>>(x2a, hT2, EDIM, gi2, Whh2, bhh2, 2, 4 * FB);

    // head
    head_kernel<<<1, 256>>>(out, hT2, WA, WB, b_bi, W_lin, b_lin);
}

// round 7
// speedup vs baseline: 2.5472x; 1.6730x over previous
#include <cuda_runtime.h>
#include <cstdint>

#define EDIM 512
#define JDIM 1536
#define TLEN 256
#define NBLK 32      // blocks per sentence per layer in the scan
#define POOL 128

// ---------------- scratch layout (floats) ----------------
#define OFF_XA   0
#define OFF_XB   (OFF_XA + 2*TLEN*EDIM)          // layer-0 trace epoch0
#define OFF_XC   (OFF_XB + 2*TLEN*EDIM)          // layer-1 trace epoch0
#define OFF_GI   (OFF_XC + 2*TLEN*EDIM)
#define OFF_FIN  (OFF_GI + 2*TLEN*JDIM)          // finals epoch0: [s][l][EDIM]
#define OFF_X2A  (OFF_FIN + 2*2*EDIM)            // layer-0 trace epoch1
#define OFF_X2B  (OFF_X2A + 2*2*EDIM)            // layer-1 trace epoch1
#define OFF_X2C  (OFF_X2B + 2*2*EDIM)            // rnn2 trace
#define OFF_FIN2 (OFF_X2C + 2*2*EDIM)            // finals epoch1: [s][l][EDIM]
#define OFF_SEQ  (OFF_FIN2 + 2*2*EDIM)           // [s][l][POOL]
#define OFF_GI2  (OFF_SEQ + 2*2*POOL)            // [s][t][JDIM]
#define OFF_HT2  (OFF_GI2 + 2*2*JDIM)            // [s][EDIM]
#define SCRATCH_SZ (OFF_HT2 + 2*EDIM)

__device__ float d_scratch[SCRATCH_SZ];
// flag regions: [(layer*2+s)][block] — 4 regions x 32 u32 = 4 x 128B lines
__device__ __align__(128) unsigned g_flags[4 * NBLK];

__device__ __forceinline__ float sigf(float x) {
    return __fdividef(1.f, 1.f + __expf(-x));
}

__device__ __forceinline__ void flag_release(unsigned* p, unsigned v) {
    asm volatile("fence.acq_rel.gpu;" ::: "memory");
    asm volatile("st.relaxed.gpu.global.u32 [%0], %1;" :: "l"(p), "r"(v) : "memory");
}
__device__ __forceinline__ unsigned flag_acquire(const unsigned* p) {
    unsigned v;
    asm volatile("ld.acquire.gpu.global.u32 %0, [%1];" : "=r"(v) : "l"(p) : "memory");
    return v;
}

__device__ __forceinline__ float4 ldcg4(const float4* p) {
    float4 v;
    asm volatile("ld.global.cg.v4.f32 {%0,%1,%2,%3}, [%4];"
                 : "=f"(v.x), "=f"(v.y), "=f"(v.z), "=f"(v.w) : "l"(p));
    return v;
}

// ---------------- embedding gather (zeroes all scan flags each replay) ----------------
__global__ void embed_kernel(float* __restrict__ x, const int* __restrict__ sA,
                             const int* __restrict__ sB, const float* __restrict__ emb) {
    const int t = blockIdx.x, s = blockIdx.y;
    if (t == 0 && s == 0 && threadIdx.x < 4 * NBLK) g_flags[threadIdx.x] = 0u;
    const int idx = (s == 0) ? sA[t] : sB[t];
    const float4* src = reinterpret_cast<const float4*>(emb + (size_t)idx * EDIM);
    float4* dst = reinterpret_cast<float4*>(x + ((size_t)s * TLEN + t) * EDIM);
    dst[threadIdx.x] = src[threadIdx.x];
}

// ---------------- gi = X @ W^T + b  (tiled, layer-0 epoch-0) ----------------
__global__ void __launch_bounds__(256) gemm_gi_kernel(
    float* __restrict__ gi, const float* __restrict__ X,
    const float* __restrict__ W, const float* __restrict__ bias, int L) {
    const int s  = blockIdx.z;
    const int t0 = blockIdx.y * 64;
    const int j0 = blockIdx.x * 64;
    __shared__ float xs[16][68];
    __shared__ float ws[16][68];
    const int tid = threadIdx.x;
    const int tx = tid & 15, ty = tid >> 4;
    float acc[4][4];
#pragma unroll
    for (int i = 0; i < 4; i++)
#pragma unroll
        for (int q = 0; q < 4; q++) acc[i][q] = 0.f;

    const float* Xs = X + (size_t)s * L * EDIM;
    for (int k0 = 0; k0 < EDIM; k0 += 16) {
#pragma unroll
        for (int i = 0; i < 4; i++) {
            const int r = ty + 16 * i;
            const int t = t0 + r;
            xs[tx][r] = (t < L) ? Xs[(size_t)t * EDIM + k0 + tx] : 0.f;
            ws[tx][r] = W[(size_t)(j0 + r) * EDIM + k0 + tx];
        }
        __syncthreads();
#pragma unroll
        for (int kk = 0; kk < 16; kk++) {
            float a[4], bb[4];
#pragma unroll
            for (int i = 0; i < 4; i++) { a[i] = xs[kk][ty * 4 + i]; bb[i] = ws[kk][tx * 4 + i]; }
#pragma unroll
            for (int i = 0; i < 4; i++)
#pragma unroll
                for (int q = 0; q < 4; q++) acc[i][q] += a[i] * bb[q];
        }
        __syncthreads();
    }
#pragma unroll
    for (int i = 0; i < 4; i++) {
        const int t = t0 + ty * 4 + i;
        if (t < L) {
#pragma unroll
            for (int q = 0; q < 4; q++) {
                const int j = j0 + tx * 4 + q;
                gi[((size_t)s * L + t) * JDIM + j] = acc[i][q] + bias[j];
            }
        }
    }
}

// ---------------- gi for L==2 sequences (epoch-1 layer 0) ----------------
__global__ void gi_small_kernel(float* __restrict__ gi, const float* __restrict__ X,
                                const float* __restrict__ W, const float* __restrict__ bias) {
    const int s = blockIdx.y;
    const int j = blockIdx.x * 256 + threadIdx.x;
    __shared__ float sx[2 * EDIM];
    for (int i = threadIdx.x; i < 2 * EDIM; i += 256) sx[i] = X[(size_t)s * 2 * EDIM + i];
    __syncthreads();
    const float* wr = W + (size_t)j * EDIM;
    float a0 = bias[j], a1 = a0;
#pragma unroll 4
    for (int k = 0; k < EDIM; k += 4) {
        const float4 w4 = *reinterpret_cast<const float4*>(wr + k);
        a0 += w4.x * sx[k] + w4.y * sx[k + 1] + w4.z * sx[k + 2] + w4.w * sx[k + 3];
        a1 += w4.x * sx[EDIM + k] + w4.y * sx[EDIM + k + 1] + w4.z * sx[EDIM + k + 2] + w4.w * sx[EDIM + k + 3];
    }
    gi[((size_t)s * 2 + 0) * JDIM + j] = a0;
    gi[((size_t)s * 2 + 1) * JDIM + j] = a1;
}

// ---------------- fused pipelined 2-layer GRU scan ----------------
// grid (NBLK, 2 sentences, nlayers). Block owns 16 h-elements; weights in regs.
// Thread (e = tid>>4, kc = tid&15): rows {elem, elem+512, elem+1024},
// k4-chunks {kc, kc+16, ..., kc+112}  — weight regs and activation reads use
// the SAME strided index (this pairing was broken in R4-R6).
__global__ void __launch_bounds__(256, 1) fused_scan_kernel(
    float* __restrict__ x0_trace, float* __restrict__ x1_trace,
    float* __restrict__ hT, int hTs,
    const float* __restrict__ gi,
    const float* __restrict__ Whh0, const float* __restrict__ bhh0,
    const float* __restrict__ Wih1, const float* __restrict__ bih1,
    const float* __restrict__ Whh1, const float* __restrict__ bhh1,
    int L, unsigned base) {
    const int s = blockIdx.y, b = blockIdx.x, layer = blockIdx.z;
    const int tid = threadIdx.x;
    const int e = tid >> 4, kc = tid & 15;
    const int elem = b * 16 + e;
    unsigned* flags0 = g_flags + (0 * 2 + s) * NBLK;
    unsigned* flags1 = g_flags + (2 + s) * NBLK;
    unsigned* myflag = (layer ? flags1 : flags0) + b;

    const float* Whh = layer ? Whh1 : Whh0;
    const float* bhh = layer ? bhh1 : bhh0;

    // recurrent weights -> registers, at k4 = kc + u*16 (matches compute reads)
    float4 wr[8], wz[8], wn[8];
    {
        const float4* Rr = reinterpret_cast<const float4*>(Whh + (size_t)elem * EDIM);
        const float4* Rz = reinterpret_cast<const float4*>(Whh + (size_t)(EDIM + elem) * EDIM);
        const float4* Rn = reinterpret_cast<const float4*>(Whh + (size_t)(2 * EDIM + elem) * EDIM);
#pragma unroll
        for (int u = 0; u < 8; u++) {
            wr[u] = Rr[kc + u * 16];
            wz[u] = Rz[kc + u * 16];
            wn[u] = Rn[kc + u * 16];
        }
    }
    const float bhr = bhh[elem], bhz = bhh[EDIM + elem], bhn = bhh[2 * EDIM + elem];

    // layer-1 input weights -> registers (same strided index)
    float4 ur[8], uz[8], un[8];
    float bir = 0.f, biz = 0.f, bin = 0.f;
    if (layer) {
        const float4* Ur = reinterpret_cast<const float4*>(Wih1 + (size_t)elem * EDIM);
        const float4* Uz = reinterpret_cast<const float4*>(Wih1 + (size_t)(EDIM + elem) * EDIM);
        const float4* Un = reinterpret_cast<const float4*>(Wih1 + (size_t)(2 * EDIM + elem) * EDIM);
#pragma unroll
        for (int u = 0; u < 8; u++) {
            ur[u] = Ur[kc + u * 16];
            uz[u] = Uz[kc + u * 16];
            un[u] = Un[kc + u * 16];
        }
        bir = bih1[elem]; biz = bih1[EDIM + elem]; bin = bih1[2 * EDIM + elem];
    }

    __shared__ float sx[EDIM];    // layer-1: x0[t]
    __shared__ float shh[EDIM];   // own h[t-1]

    const float* x0 = x0_trace + (size_t)s * L * EDIM;
    float* xo = (layer ? x1_trace : x0_trace) + (size_t)s * L * EDIM;
    const float* gs = gi + (size_t)s * L * JDIM;

    for (int t = 0; t < L; t++) {
        // prefetch layer-0 input gates (overlaps the spin)
        float g0 = 0.f, g1 = 0.f, g2 = 0.f;
        if (!layer && kc == 0) {
            const float* git = gs + (size_t)t * JDIM;
            g0 = __ldcg(git + elem);
            g1 = __ldcg(git + EDIM + elem);
            g2 = __ldcg(git + 2 * EDIM + elem);
        }
        // spin phase
        if (layer) {
            if (tid < NBLK) {
                const unsigned* fp = &flags0[tid];
                const unsigned tgt = base + (unsigned)t + 1u;    // x0 row t ready
                while (flag_acquire(fp) < tgt) { }
            } else if (tid < 2 * NBLK && t > 0) {
                const unsigned* fp = &flags1[tid - NBLK];
                const unsigned tgt = base + (unsigned)t;         // own row t-1 ready
                while (flag_acquire(fp) < tgt) { }
            }
        } else if (t > 0 && tid < NBLK) {
            const unsigned* fp = &flags0[tid];
            const unsigned tgt = base + (unsigned)t;
            while (flag_acquire(fp) < tgt) { }
        }
        __syncthreads();
        // stage
        if (layer && tid < 128)
            reinterpret_cast<float4*>(sx)[tid] =
                ldcg4(reinterpret_cast<const float4*>(x0 + (size_t)t * EDIM) + tid);
        if (tid >= 128) {
            if (t > 0)
                reinterpret_cast<float4*>(shh)[tid - 128] =
                    ldcg4(reinterpret_cast<const float4*>(xo + (size_t)(t - 1) * EDIM) + (tid - 128));
            else
                reinterpret_cast<float4*>(shh)[tid - 128] = make_float4(0.f, 0.f, 0.f, 0.f);
        }
        __syncthreads();

        // matvecs (activation index kc + u*16 == weight-register index)
        float pr = 0.f, pz = 0.f, pn = 0.f;
        float qr = 0.f, qz = 0.f, qn = 0.f;
#pragma unroll
        for (int u = 0; u < 8; u++) {
            const float4 h4 = reinterpret_cast<const float4*>(shh)[kc + u * 16];
            pr += wr[u].x * h4.x; pr += wr[u].y * h4.y; pr += wr[u].z * h4.z; pr += wr[u].w * h4.w;
            pz += wz[u].x * h4.x; pz += wz[u].y * h4.y; pz += wz[u].z * h4.z; pz += wz[u].w * h4.w;
            pn += wn[u].x * h4.x; pn += wn[u].y * h4.y; pn += wn[u].z * h4.z; pn += wn[u].w * h4.w;
        }
        if (layer) {
#pragma unroll
            for (int u = 0; u < 8; u++) {
                const float4 x4 = reinterpret_cast<const float4*>(sx)[kc + u * 16];
                qr += ur[u].x * x4.x; qr += ur[u].y * x4.y; qr += ur[u].z * x4.z; qr += ur[u].w * x4.w;
                qz += uz[u].x * x4.x; qz += uz[u].y * x4.y; qz += uz[u].z * x4.z; qz += uz[u].w * x4.w;
                qn += un[u].x * x4.x; qn += un[u].y * x4.y; qn += un[u].z * x4.z; qn += un[u].w * x4.w;
            }
        }
#pragma unroll
        for (int off = 8; off > 0; off >>= 1) {
            pr += __shfl_down_sync(0xffffffffu, pr, off, 16);
            pz += __shfl_down_sync(0xffffffffu, pz, off, 16);
            pn += __shfl_down_sync(0xffffffffu, pn, off, 16);
        }
        if (layer) {
#pragma unroll
            for (int off = 8; off > 0; off >>= 1) {
                qr += __shfl_down_sync(0xffffffffu, qr, off, 16);
                qz += __shfl_down_sync(0xffffffffu, qz, off, 16);
                qn += __shfl_down_sync(0xffffffffu, qn, off, 16);
            }
        }
        if (kc == 0) {
            if (layer) { g0 = qr + bir; g1 = qz + biz; g2 = qn + bin; }  // bias added ONCE
            const float hold = shh[elem];
            const float r = sigf(g0 + pr + bhr);
            const float z = sigf(g1 + pz + bhz);
            const float n = tanhf(g2 + r * (pn + bhn));
            const float hnew = (1.f - z) * n + z * hold;
            __stcg(xo + (size_t)t * EDIM + elem, hnew);
            if (t == L - 1) hT[s * hTs + layer * EDIM + elem] = hnew;
        }
        __syncthreads();
        if (tid == 0) flag_release(myflag, base + (unsigned)t + 1u);
    }
}

// ---------------- conv1d(stride2,pad255) + bias + global maxpool ----------------
__global__ void conv_pool_kernel(float* __restrict__ seq, const float* __restrict__ hin,
                                 const float* __restrict__ cw, const float* __restrict__ cb) {
    const int s = blockIdx.x >> 1, oc = blockIdx.x & 1;
    __shared__ float sin[2 * EDIM];
    __shared__ float sw[2 * EDIM];
    __shared__ float red[256];
    const int tid = threadIdx.x;
    for (int i = tid; i < 2 * EDIM; i += 256) {
        sin[i] = hin[(size_t)s * 2 * EDIM + i];
        sw[i]  = cw[(size_t)oc * 2 * EDIM + i];
    }
    __syncthreads();
    float v = cb[oc];
    const int base = 2 * tid - 255;
    for (int k = 0; k < EDIM; k++) {
        const int pos = base + k;
        if (pos >= 0 && pos < EDIM)
            v += sw[k] * sin[pos] + sw[EDIM + k] * sin[EDIM + pos];
    }
    red[tid] = v;
    __syncthreads();
    for (int off = 128; off > 0; off >>= 1) {
        if (tid < off) red[tid] = fmaxf(red[tid], red[tid + off]);
        __syncthreads();
    }
    const float M = red[0];
    if (tid < POOL) seq[((size_t)s * 2 + oc) * POOL + tid] = M;
}

// ---------------- gi2 = seq @ Wih2^T + bih2 (K=128, L=2) ----------------
__global__ void gi2_kernel(float* __restrict__ gi2, const float* __restrict__ seq,
                           const float* __restrict__ W2, const float* __restrict__ b2) {
    const int j = blockIdx.x * 256 + threadIdx.x;
    const int t = blockIdx.y, s = blockIdx.z;
    __shared__ float ss[POOL];
    if (threadIdx.x < POOL) ss[threadIdx.x] = seq[((size_t)s * 2 + t) * POOL + threadIdx.x];
    __syncthreads();
    const float* wr = W2 + (size_t)j * POOL;
    float acc = b2[j];
#pragma unroll 4
    for (int q = 0; q < POOL; q += 4) {
        const float4 w4 = *reinterpret_cast<const float4*>(wr + q);
        acc += w4.x * ss[q] + w4.y * ss[q + 1] + w4.z * ss[q + 2] + w4.w * ss[q + 3];
    }
    gi2[((size_t)s * 2 + t) * JDIM + j] = acc;
}

// ---------------- head ----------------
__global__ void head_kernel(float* __restrict__ out, const float* __restrict__ hT2,
                            const float* __restrict__ WA, const float* __restrict__ WB,
                            const float* __restrict__ b_bi, const float* __restrict__ Wlin,
                            const float* __restrict__ blin) {
    const int j = threadIdx.x;
    __shared__ float shx[EDIM];
    __shared__ float shv[EDIM];
    __shared__ float red[256];
    for (int k = j; k < EDIM; k += 256) {
        const float a = hT2[k], b = hT2[EDIM + k];
        shx[k] = a * b;
        shv[k] = fabsf(a - b);
    }
    __syncthreads();
    float acc = b_bi[j];
    for (int k = 0; k < EDIM; k++)
        acc += shx[k] * WA[(size_t)k * 256 + j] + shv[k] * WB[(size_t)k * 256 + j];
    const float ht = tanhf(acc);
    red[j] = ht * Wlin[j];
    __syncthreads();
    for (int off = 128; off > 0; off >>= 1) {
        if (j < off) red[j] += red[j + off];
        __syncthreads();
    }
    if (j == 0) out[0] = 1.f / (1.f + __expf(-(red[0] + blin[0])));
}

// ---------------- launch ----------------
extern "C" void kernel_launch(void* const* d_in, const int* in_sizes, int n_in,
                              void* d_out, int out_size) {
    const int*   sentA  = (const int*)  d_in[0];
    const int*   sentB  = (const int*)  d_in[1];
    const float* emb    = (const float*)d_in[2];
    const float* Wih1   = (const float*)d_in[3];
    const float* Whh1   = (const float*)d_in[4];
    const float* bih1   = (const float*)d_in[5];
    const float* bhh1   = (const float*)d_in[6];
    const float* conv_w = (const float*)d_in[7];
    const float* conv_b = (const float*)d_in[8];
    const float* Wih2   = (const float*)d_in[9];
    const float* Whh2   = (const float*)d_in[10];
    const float* bih2   = (const float*)d_in[11];
    const float* bhh2   = (const float*)d_in[12];
    const float* WA     = (const float*)d_in[13];
    const float* WB     = (const float*)d_in[14];
    const float* b_bi   = (const float*)d_in[15];
    const float* W_lin  = (const float*)d_in[16];
    const float* b_lin  = (const float*)d_in[17];
    float* out = (float*)d_out;

    float* S = nullptr;
    cudaGetSymbolAddress((void**)&S, d_scratch);

    float* xA   = S + OFF_XA;
    float* xB   = S + OFF_XB;
    float* xC   = S + OFF_XC;
    float* gi   = S + OFF_GI;
    float* fin  = S + OFF_FIN;
    float* x2a  = S + OFF_X2A;
    float* x2b  = S + OFF_X2B;
    float* x2c  = S + OFF_X2C;
    float* fin2 = S + OFF_FIN2;
    float* seq  = S + OFF_SEQ;
    float* gi2  = S + OFF_GI2;
    float* hT2  = S + OFF_HT2;

    const size_t WSTRIDE = (size_t)JDIM * EDIM;

    // embedding (zeroes flags each replay)
    embed_kernel<<<dim3(TLEN, 2), 128>>>(xA, sentA, sentB, emb);

    // ---- epoch 0: gi for layer 0, then pipelined 2-layer scan ----
    gemm_gi_kernel<<<dim3(JDIM / 64, TLEN / 64, 2), 256>>>(gi, xA, Wih1, bih1, TLEN);
    fused_scan_kernel<<<dim3(NBLK, 2, 2), 256>>>(
        xB, xC, fin, 2 * EDIM, gi,
        Whh1, bhh1,
        Wih1 + WSTRIDE, bih1 + JDIM, Whh1 + WSTRIDE, bhh1 + JDIM,
        TLEN, 0u);

    // ---- epoch 1 (L = 2): gi for layer 0, pipelined 2-layer scan ----
    gi_small_kernel<<<dim3(JDIM / 256, 2), 256>>>(gi, fin, Wih1, bih1);
    fused_scan_kernel<<<dim3(NBLK, 2, 2), 256>>>(
        x2a, x2b, fin2, 2 * EDIM, gi,
        Whh1, bhh1,
        Wih1 + WSTRIDE, bih1 + JDIM, Whh1 + WSTRIDE, bhh1 + JDIM,
        2, (unsigned)TLEN);

    // conv + pool
    conv_pool_kernel<<<4, 256>>>(seq, fin2, conv_w, conv_b);

    // rnn_second (single layer, L = 2)
    gi2_kernel<<<dim3(JDIM / 256, 2, 2), 256>>>(gi2, seq, Wih2, bih2);
    fused_scan_kernel<<<dim3(NBLK, 2, 1), 256>>>(
        x2c, x2b, hT2, EDIM, gi2,
        Whh2, bhh2,
        Wih2, bih2, Whh2, bhh2,
        2, (unsigned)TLEN + 2u);

    // head
    head_kernel<<<1, 256>>>(out, hT2, WA, WB, b_bi, W_lin, b_lin);
}

// round 10
// speedup vs baseline: 3.1192x; 1.2245x over previous
#include <cuda_runtime.h>
#include <cstdint>

#define EDIM 512
#define JDIM 1536
#define TLEN 256
#define NBLK 32      // blocks per sentence per layer in the scan
#define POOL 128

// ---------------- scratch layout (floats) ----------------
#define OFF_XA   0
#define OFF_XB   (OFF_XA + 2*TLEN*EDIM)          // layer-0 trace epoch0
#define OFF_XC   (OFF_XB + 2*TLEN*EDIM)          // layer-1 trace epoch0
#define OFF_GI   (OFF_XC + 2*TLEN*EDIM)          // used only by gi2 now
#define OFF_FIN  (OFF_GI + 2*TLEN*JDIM)          // finals epoch0: [s][l][EDIM]
#define OFF_X2A  (OFF_FIN + 2*2*EDIM)            // layer-0 trace epoch1
#define OFF_X2B  (OFF_X2A + 2*2*EDIM)            // layer-1 trace epoch1
#define OFF_X2C  (OFF_X2B + 2*2*EDIM)            // rnn2 trace
#define OFF_FIN2 (OFF_X2C + 2*2*EDIM)            // finals epoch1: [s][l][EDIM]
#define OFF_SEQ  (OFF_FIN2 + 2*2*EDIM)           // [s][l][POOL]
#define OFF_GI2  (OFF_SEQ + 2*2*POOL)            // [s][t][JDIM]
#define OFF_HT2  (OFF_GI2 + 2*2*JDIM)            // [s][EDIM]
#define SCRATCH_SZ (OFF_HT2 + 2*EDIM)

__device__ float d_scratch[SCRATCH_SZ];
// flag regions: [(layer*2+s)][block] — 4 regions x 32 u32 = 4 x 128B lines
__device__ __align__(128) unsigned g_flags[4 * NBLK];

__device__ __forceinline__ float sigf(float x) {
    return __fdividef(1.f, 1.f + __expf(-x));
}

__device__ __forceinline__ void flag_release(unsigned* p, unsigned v) {
    asm volatile("fence.acq_rel.gpu;" ::: "memory");
    asm volatile("st.relaxed.gpu.global.u32 [%0], %1;" :: "l"(p), "r"(v) : "memory");
}
__device__ __forceinline__ unsigned flag_acquire(const unsigned* p) {
    unsigned v;
    asm volatile("ld.acquire.gpu.global.u32 %0, [%1];" : "=r"(v) : "l"(p) : "memory");
    return v;
}

__device__ __forceinline__ float4 ldcg4(const float4* p) {
    float4 v;
    asm volatile("ld.global.cg.v4.f32 {%0,%1,%2,%3}, [%4];"
                 : "=f"(v.x), "=f"(v.y), "=f"(v.z), "=f"(v.w) : "l"(p));
    return v;
}

// ---------------- embedding gather (zeroes all scan flags each replay) ----------------
__global__ void embed_kernel(float* __restrict__ x, const int* __restrict__ sA,
                             const int* __restrict__ sB, const float* __restrict__ emb) {
    const int t = blockIdx.x, s = blockIdx.y;
    if (t == 0 && s == 0 && threadIdx.x < 4 * NBLK) g_flags[threadIdx.x] = 0u;
    const int idx = (s == 0) ? sA[t] : sB[t];
    const float4* src = reinterpret_cast<const float4*>(emb + (size_t)idx * EDIM);
    float4* dst = reinterpret_cast<float4*>(x + ((size_t)s * TLEN + t) * EDIM);
    dst[threadIdx.x] = src[threadIdx.x];
}

// ---------------- fused pipelined 2-layer GRU scan (R7 flag protocol) ----------------
// grid (NBLK, 2 sentences, nlayers). Block owns 16 h-elements; weights in regs
// at k4 = kc + u*16 (matches activation reads).
// fly = (layer==1) || !use_gi: input gates computed on the fly from the input
// sequence (layer 0: x_in, pre-launch-ready, no producer wait; layer 1:
// x0_trace, waits flags0). use_gi=1 layer 0 (rnn2) reads precomputed gi.
// Recurrence sync: Round-3/7 release/acquire per-block flag counters,
// flag = base + (#trace rows written). Unchanged from the passing R7 kernel.
__global__ void __launch_bounds__(256, 1) fused_scan_kernel(
    float* __restrict__ x0_trace, float* __restrict__ x1_trace,
    float* __restrict__ hT, int hTs,
    const float* __restrict__ gi, int use_gi,
    const float* __restrict__ x_in,
    const float* __restrict__ Wih0, const float* __restrict__ bih0,
    const float* __restrict__ Whh0, const float* __restrict__ bhh0,
    const float* __restrict__ Wih1, const float* __restrict__ bih1,
    const float* __restrict__ Whh1, const float* __restrict__ bhh1,
    int L, unsigned base) {
    const int s = blockIdx.y, b = blockIdx.x, layer = blockIdx.z;
    const int tid = threadIdx.x;
    const int e = tid >> 4, kc = tid & 15;
    const int elem = b * 16 + e;
    unsigned* flags0 = g_flags + (0 * 2 + s) * NBLK;
    unsigned* flags1 = g_flags + (2 + s) * NBLK;
    unsigned* myflag = (layer ? flags1 : flags0) + b;
    const bool fly = (layer == 1) || !use_gi;

    const float* Whh = layer ? Whh1 : Whh0;
    const float* bhh = layer ? bhh1 : bhh0;

    // recurrent weights -> registers at k4 = kc + u*16 (matches compute reads)
    float4 wr[8], wz[8], wn[8];
    {
        const float4* Rr = reinterpret_cast<const float4*>(Whh + (size_t)elem * EDIM);
        const float4* Rz = reinterpret_cast<const float4*>(Whh + (size_t)(EDIM + elem) * EDIM);
        const float4* Rn = reinterpret_cast<const float4*>(Whh + (size_t)(2 * EDIM + elem) * EDIM);
#pragma unroll
        for (int u = 0; u < 8; u++) {
            wr[u] = Rr[kc + u * 16];
            wz[u] = Rz[kc + u * 16];
            wn[u] = Rn[kc + u * 16];
        }
    }
    const float bhr = bhh[elem], bhz = bhh[EDIM + elem], bhn = bhh[2 * EDIM + elem];

    // input-gate weights -> registers (same strided index) when flying
    float4 ur[8], uz[8], un[8];
    float bir = 0.f, biz = 0.f, bin = 0.f;
    if (fly) {
        const float* U  = layer ? Wih1 : Wih0;
        const float* bi = layer ? bih1 : bih0;
        const float4* Ur = reinterpret_cast<const float4*>(U + (size_t)elem * EDIM);
        const float4* Uz = reinterpret_cast<const float4*>(U + (size_t)(EDIM + elem) * EDIM);
        const float4* Un = reinterpret_cast<const float4*>(U + (size_t)(2 * EDIM + elem) * EDIM);
#pragma unroll
        for (int u = 0; u < 8; u++) {
            ur[u] = Ur[kc + u * 16];
            uz[u] = Uz[kc + u * 16];
            un[u] = Un[kc + u * 16];
        }
        bir = bi[elem]; biz = bi[EDIM + elem]; bin = bi[2 * EDIM + elem];
    }

    __shared__ float sx[EDIM];    // input x[t] (fly mode)
    __shared__ float shh[EDIM];   // own h[t-1]

    const float* xin = layer ? (x0_trace + (size_t)s * L * EDIM)
                             : (fly ? (x_in + (size_t)s * L * EDIM) : nullptr);
    float* xo = (layer ? x1_trace : x0_trace) + (size_t)s * L * EDIM;
    const float* gs = gi + (size_t)s * L * JDIM;

    for (int t = 0; t < L; t++) {
        // prefetch precomputed input gates (overlaps the spin) — use_gi path only
        float g0 = 0.f, g1 = 0.f, g2 = 0.f;
        if (!fly && kc == 0) {
            const float* git = gs + (size_t)t * JDIM;
            g0 = __ldcg(git + elem);
            g1 = __ldcg(git + EDIM + elem);
            g2 = __ldcg(git + 2 * EDIM + elem);
        }
        // spin phase (R7 exact)
        if (layer) {
            if (tid < NBLK) {
                const unsigned* fp = &flags0[tid];
                const unsigned tgt = base + (unsigned)t + 1u;    // x0 row t ready
                while (flag_acquire(fp) < tgt) { }
            } else if (tid < 2 * NBLK && t > 0) {
                const unsigned* fp = &flags1[tid - NBLK];
                const unsigned tgt = base + (unsigned)t;         // own row t-1 ready
                while (flag_acquire(fp) < tgt) { }
            }
        } else if (t > 0 && tid < NBLK) {
            const unsigned* fp = &flags0[tid];
            const unsigned tgt = base + (unsigned)t;
            while (flag_acquire(fp) < tgt) { }
        }
        __syncthreads();
        // stage input x (lower half) and own h (upper half)
        if (fly && tid < 128)
            reinterpret_cast<float4*>(sx)[tid] =
                ldcg4(reinterpret_cast<const float4*>(xin + (size_t)t * EDIM) + tid);
        if (tid >= 128) {
            const int i = tid - 128;
            if (t > 0)
                reinterpret_cast<float4*>(shh)[i] =
                    ldcg4(reinterpret_cast<const float4*>(xo + (size_t)(t - 1) * EDIM) + i);
            else
                reinterpret_cast<float4*>(shh)[i] = make_float4(0.f, 0.f, 0.f, 0.f);
        }
        __syncthreads();

        // matvecs (activation index kc + u*16 == weight-register index)
        float pr = 0.f, pz = 0.f, pn = 0.f;
        float qr = 0.f, qz = 0.f, qn = 0.f;
#pragma unroll
        for (int u = 0; u < 8; u++) {
            const float4 h4 = reinterpret_cast<const float4*>(shh)[kc + u * 16];
            pr += wr[u].x * h4.x; pr += wr[u].y * h4.y; pr += wr[u].z * h4.z; pr += wr[u].w * h4.w;
            pz += wz[u].x * h4.x; pz += wz[u].y * h4.y; pz += wz[u].z * h4.z; pz += wz[u].w * h4.w;
            pn += wn[u].x * h4.x; pn += wn[u].y * h4.y; pn += wn[u].z * h4.z; pn += wn[u].w * h4.w;
        }
        if (fly) {
#pragma unroll
            for (int u = 0; u < 8; u++) {
                const float4 x4 = reinterpret_cast<const float4*>(sx)[kc + u * 16];
                qr += ur[u].x * x4.x; qr += ur[u].y * x4.y; qr += ur[u].z * x4.z; qr += ur[u].w * x4.w;
                qz += uz[u].x * x4.x; qz += uz[u].y * x4.y; qz += uz[u].z * x4.z; qz += uz[u].w * x4.w;
                qn += un[u].x * x4.x; qn += un[u].y * x4.y; qn += un[u].z * x4.z; qn += un[u].w * x4.w;
            }
        }
#pragma unroll
        for (int off = 8; off > 0; off >>= 1) {
            pr += __shfl_down_sync(0xffffffffu, pr, off, 16);
            pz += __shfl_down_sync(0xffffffffu, pz, off, 16);
            pn += __shfl_down_sync(0xffffffffu, pn, off, 16);
        }
        if (fly) {
#pragma unroll
            for (int off = 8; off > 0; off >>= 1) {
                qr += __shfl_down_sync(0xffffffffu, qr, off, 16);
                qz += __shfl_down_sync(0xffffffffu, qz, off, 16);
                qn += __shfl_down_sync(0xffffffffu, qn, off, 16);
            }
        }
        if (kc == 0) {
            if (fly) { g0 = qr + bir; g1 = qz + biz; g2 = qn + bin; }  // bias added ONCE
            const float hold = shh[elem];
            const float r = sigf(g0 + pr + bhr);
            const float z = sigf(g1 + pz + bhz);
            const float n = tanhf(g2 + r * (pn + bhn));
            const float hnew = (1.f - z) * n + z * hold;
            __stcg(xo + (size_t)t * EDIM + elem, hnew);
            if (t == L - 1) hT[s * hTs + layer * EDIM + elem] = hnew;
        }
        __syncthreads();
        if (tid == 0) flag_release(myflag, base + (unsigned)t + 1u);
    }
}

// ---------------- conv1d(stride2,pad255) + bias + global maxpool ----------------
__global__ void conv_pool_kernel(float* __restrict__ seq, const float* __restrict__ hin,
                                 const float* __restrict__ cw, const float* __restrict__ cb) {
    const int s = blockIdx.x >> 1, oc = blockIdx.x & 1;
    __shared__ float sin[2 * EDIM];
    __shared__ float sw[2 * EDIM];
    __shared__ float red[256];
    const int tid = threadIdx.x;
    for (int i = tid; i < 2 * EDIM; i += 256) {
        sin[i] = hin[(size_t)s * 2 * EDIM + i];
        sw[i]  = cw[(size_t)oc * 2 * EDIM + i];
    }
    __syncthreads();
    float v = cb[oc];
    const int base = 2 * tid - 255;
    for (int k = 0; k < EDIM; k++) {
        const int pos = base + k;
        if (pos >= 0 && pos < EDIM)
            v += sw[k] * sin[pos] + sw[EDIM + k] * sin[EDIM + pos];
    }
    red[tid] = v;
    __syncthreads();
    for (int off = 128; off > 0; off >>= 1) {
        if (tid < off) red[tid] = fmaxf(red[tid], red[tid + off]);
        __syncthreads();
    }
    const float M = red[0];
    if (tid < POOL) seq[((size_t)s * 2 + oc) * POOL + tid] = M;
}

// ---------------- gi2 = seq @ Wih2^T + bih2 (K=128, L=2) ----------------
__global__ void gi2_kernel(float* __restrict__ gi2, const float* __restrict__ seq,
                           const float* __restrict__ W2, const float* __restrict__ b2) {
    const int j = blockIdx.x * 256 + threadIdx.x;
    const int t = blockIdx.y, s = blockIdx.z;
    __shared__ float ss[POOL];
    if (threadIdx.x < POOL) ss[threadIdx.x] = seq[((size_t)s * 2 + t) * POOL + threadIdx.x];
    __syncthreads();
    const float* wr = W2 + (size_t)j * POOL;
    float acc = b2[j];
#pragma unroll 4
    for (int q = 0; q < POOL; q += 4) {
        const float4 w4 = *reinterpret_cast<const float4*>(wr + q);
        acc += w4.x * ss[q] + w4.y * ss[q + 1] + w4.z * ss[q + 2] + w4.w * ss[q + 3];
    }
    gi2[((size_t)s * 2 + t) * JDIM + j] = acc;
}

// ---------------- head ----------------
__global__ void head_kernel(float* __restrict__ out, const float* __restrict__ hT2,
                            const float* __restrict__ WA, const float* __restrict__ WB,
                            const float* __restrict__ b_bi, const float* __restrict__ Wlin,
                            const float* __restrict__ blin) {
    const int j = threadIdx.x;
    __shared__ float shx[EDIM];
    __shared__ float shv[EDIM];
    __shared__ float red[256];
    for (int k = j; k < EDIM; k += 256) {
        const float a = hT2[k], b = hT2[EDIM + k];
        shx[k] = a * b;
        shv[k] = fabsf(a - b);
    }
    __syncthreads();
    float acc = b_bi[j];
    for (int k = 0; k < EDIM; k++)
        acc += shx[k] * WA[(size_t)k * 256 + j] + shv[k] * WB[(size_t)k * 256 + j];
    const float ht = tanhf(acc);
    red[j] = ht * Wlin[j];
    __syncthreads();
    for (int off = 128; off > 0; off >>= 1) {
        if (j < off) red[j] += red[j + off];
        __syncthreads();
    }
    if (j == 0) out[0] = 1.f / (1.f + __expf(-(red[0] + blin[0])));
}

// ---------------- launch ----------------
extern "C" void kernel_launch(void* const* d_in, const int* in_sizes, int n_in,
                              void* d_out, int out_size) {
    const int*   sentA  = (const int*)  d_in[0];
    const int*   sentB  = (const int*)  d_in[1];
    const float* emb    = (const float*)d_in[2];
    const float* Wih1   = (const float*)d_in[3];
    const float* Whh1   = (const float*)d_in[4];
    const float* bih1   = (const float*)d_in[5];
    const float* bhh1   = (const float*)d_in[6];
    const float* conv_w = (const float*)d_in[7];
    const float* conv_b = (const float*)d_in[8];
    const float* Wih2   = (const float*)d_in[9];
    const float* Whh2   = (const float*)d_in[10];
    const float* bih2   = (const float*)d_in[11];
    const float* bhh2   = (const float*)d_in[12];
    const float* WA     = (const float*)d_in[13];
    const float* WB     = (const float*)d_in[14];
    const float* b_bi   = (const float*)d_in[15];
    const float* W_lin  = (const float*)d_in[16];
    const float* b_lin  = (const float*)d_in[17];
    float* out = (float*)d_out;

    float* S = nullptr;
    cudaGetSymbolAddress((void**)&S, d_scratch);

    float* xA   = S + OFF_XA;
    float* xB   = S + OFF_XB;
    float* xC   = S + OFF_XC;
    float* gi   = S + OFF_GI;
    float* fin  = S + OFF_FIN;
    float* x2a  = S + OFF_X2A;
    float* x2b  = S + OFF_X2B;
    float* x2c  = S + OFF_X2C;
    float* fin2 = S + OFF_FIN2;
    float* seq  = S + OFF_SEQ;
    float* gi2  = S + OFF_GI2;
    float* hT2  = S + OFF_HT2;

    const size_t WSTRIDE = (size_t)JDIM * EDIM;

    // embedding (zeroes flags each replay)
    embed_kernel<<<dim3(TLEN, 2), 128>>>(xA, sentA, sentB, emb);

    // ---- epoch 0: pipelined 2-layer scan, BOTH layers compute gates on the fly ----
    fused_scan_kernel<<<dim3(NBLK, 2, 2), 256>>>(
        xB, xC, fin, 2 * EDIM,
        gi, 0, xA,
        Wih1, bih1, Whh1, bhh1,
        Wih1 + WSTRIDE, bih1 + JDIM, Whh1 + WSTRIDE, bhh1 + JDIM,
        TLEN, 0u);

    // ---- epoch 1 (L = 2): both layers fly from fin ----
    fused_scan_kernel<<<dim3(NBLK, 2, 2), 256>>>(
        x2a, x2b, fin2, 2 * EDIM,
        gi, 0, fin,
        Wih1, bih1, Whh1, bhh1,
        Wih1 + WSTRIDE, bih1 + JDIM, Whh1 + WSTRIDE, bhh1 + JDIM,
        2, (unsigned)TLEN);

    // conv + pool
    conv_pool_kernel<<<4, 256>>>(seq, fin2, conv_w, conv_b);

    // rnn_second (single layer, L = 2, gi precomputed — K=128 input)
    gi2_kernel<<<dim3(JDIM / 256, 2, 2), 256>>>(gi2, seq, Wih2, bih2);
    fused_scan_kernel<<<dim3(NBLK, 2, 1), 256>>>(
        x2c, x2c, hT2, EDIM,
        gi2, 1, seq,
        Wih2, bih2, Whh2, bhh2,
        Wih2, bih2, Whh2, bhh2,
        2, (unsigned)TLEN + 2u);

    // head
    head_kernel<<<1, 256>>>(out, hT2, WA, WB, b_bi, W_lin, b_lin);
}

// round 12
// speedup vs baseline: 3.7085x; 1.1889x over previous
#include <cuda_runtime.h>
#include <cstdint>

#define EDIM 512
#define JDIM 1536
#define TLEN 256
#define NBLK 32      // blocks per sentence per layer in the scan
#define POOL 128

// ---------------- scratch layout (floats) ----------------
#define OFF_XA   0
#define OFF_XB   (OFF_XA + 2*TLEN*EDIM)          // layer-0 trace epoch0
#define OFF_XC   (OFF_XB + 2*TLEN*EDIM)          // layer-1 trace epoch0
#define OFF_FIN  (OFF_XC + 2*TLEN*EDIM)          // finals epoch0: [s][l][EDIM]
#define OFF_X2A  (OFF_FIN + 2*2*EDIM)            // layer-0 trace epoch1
#define OFF_X2B  (OFF_X2A + 2*2*EDIM)            // layer-1 trace epoch1
#define OFF_X2C  (OFF_X2B + 2*2*EDIM)            // rnn2 trace
#define OFF_FIN2 (OFF_X2C + 2*2*EDIM)            // finals epoch1: [s][l][EDIM]
#define OFF_SEQ  (OFF_FIN2 + 2*2*EDIM)           // [s][l][POOL]
#define OFF_HT2  (OFF_SEQ + 2*2*POOL)            // [s][EDIM]
#define SCRATCH_SZ (OFF_HT2 + 2*EDIM)

__device__ float d_scratch[SCRATCH_SZ];
// flag regions: [(layer*2+s)][block] — 4 regions x 32 u32 = 4 x 128B lines
__device__ __align__(128) unsigned g_flags[4 * NBLK];

__device__ __forceinline__ float sigf(float x) {
    return __fdividef(1.f, 1.f + __expf(-x));
}

// release-store publish: orders all prior (syncthreads-covered) stores before
// the flag becomes visible — replaces fence.acq_rel + relaxed store.
__device__ __forceinline__ void flag_release(unsigned* p, unsigned v) {
    asm volatile("st.release.gpu.global.u32 [%0], %1;" :: "l"(p), "r"(v) : "memory");
}
__device__ __forceinline__ unsigned flag_acquire(const unsigned* p) {
    unsigned v;
    asm volatile("ld.acquire.gpu.global.u32 %0, [%1];" : "=r"(v) : "l"(p) : "memory");
    return v;
}

__device__ __forceinline__ float4 ldcg4(const float4* p) {
    float4 v;
    asm volatile("ld.global.cg.v4.f32 {%0,%1,%2,%3}, [%4];"
                 : "=f"(v.x), "=f"(v.y), "=f"(v.z), "=f"(v.w) : "l"(p));
    return v;
}

// ---------------- embedding gather (zeroes all scan flags each replay) ----------------
__global__ void embed_kernel(float* __restrict__ x, const int* __restrict__ sA,
                             const int* __restrict__ sB, const float* __restrict__ emb) {
    const int t = blockIdx.x, s = blockIdx.y;
    if (t == 0 && s == 0 && threadIdx.x < 4 * NBLK) g_flags[threadIdx.x] = 0u;
    const int idx = (s == 0) ? sA[t] : sB[t];
    const float4* src = reinterpret_cast<const float4*>(emb + (size_t)idx * EDIM);
    float4* dst = reinterpret_cast<float4*>(x + ((size_t)s * TLEN + t) * EDIM);
    dst[threadIdx.x] = src[threadIdx.x];
}

// ---------------- fused pipelined 2-layer GRU scan (all gates on the fly) ----------------
// Template INF4: input dim IN = INF4*64 (8 -> 512, 2 -> 128).
// grid (NBLK, 2 sentences, nlayers). Block owns 16 h-elements; weights in regs
// at k4 = kc + u*16 (matches activation reads).
// layer 0 reads x_in (pre-launch-ready, no producer wait); layer 1 reads
// x0_trace (waits flags0). INF4==2 launches layer 0 only (layer-1 input dim
// would be EDIM; for INF4==8 they coincide, so one code path serves both).
// Recurrence sync: release/acquire per-block flag counters,
// flag = base + (#trace rows written). Protocol unchanged from R7/R10.
template <int INF4>
__global__ void __launch_bounds__(256, 1) fused_scan_kernel(
    float* __restrict__ x0_trace, float* __restrict__ x1_trace,
    float* __restrict__ hT, int hTs,
    const float* __restrict__ x_in,
    const float* __restrict__ Wih0, const float* __restrict__ bih0,
    const float* __restrict__ Whh0, const float* __restrict__ bhh0,
    const float* __restrict__ Wih1, const float* __restrict__ bih1,
    const float* __restrict__ Whh1, const float* __restrict__ bhh1,
    int L, unsigned base) {
    constexpr int IN = INF4 * 64;
    const int s = blockIdx.y, b = blockIdx.x, layer = blockIdx.z;
    if (INF4 != 8 && layer != 0) return;   // never launched; keeps one code path
    const int tid = threadIdx.x;
    const int e = tid >> 4, kc = tid & 15;
    const int elem = b * 16 + e;
    unsigned* flags0 = g_flags + (0 * 2 + s) * NBLK;
    unsigned* flags1 = g_flags + (2 + s) * NBLK;
    unsigned* myflag = (layer ? flags1 : flags0) + b;

    const float* Whh = layer ? Whh1 : Whh0;
    const float* bhh = layer ? bhh1 : bhh0;

    // recurrent weights -> registers at k4 = kc + u*16 (hidden dim is always 512)
    float4 wr[8], wz[8], wn[8];
    {
        const float4* Rr = reinterpret_cast<const float4*>(Whh + (size_t)elem * EDIM);
        const float4* Rz = reinterpret_cast<const float4*>(Whh + (size_t)(EDIM + elem) * EDIM);
        const float4* Rn = reinterpret_cast<const float4*>(Whh + (size_t)(2 * EDIM + elem) * EDIM);
#pragma unroll
        for (int u = 0; u < 8; u++) {
            wr[u] = Rr[kc + u * 16];
            wz[u] = Rz[kc + u * 16];
            wn[u] = Rn[kc + u * 16];
        }
    }
    const float bhr = bhh[elem], bhz = bhh[EDIM + elem], bhn = bhh[2 * EDIM + elem];

    // input-gate weights -> registers (input dim IN; layer 1 only exists for IN==512)
    float4 ur[INF4], uz[INF4], un[INF4];
    float bir, biz, bin;
    {
        const float* U  = layer ? Wih1 : Wih0;
        const float* bi = layer ? bih1 : bih0;
        const float4* Ur = reinterpret_cast<const float4*>(U + (size_t)elem * IN);
        const float4* Uz = reinterpret_cast<const float4*>(U + (size_t)(EDIM + elem) * IN);
        const float4* Un = reinterpret_cast<const float4*>(U + (size_t)(2 * EDIM + elem) * IN);
#pragma unroll
        for (int u = 0; u < INF4; u++) {
            ur[u] = Ur[kc + u * 16];
            uz[u] = Uz[kc + u * 16];
            un[u] = Un[kc + u * 16];
        }
        bir = bi[elem]; biz = bi[EDIM + elem]; bin = bi[2 * EDIM + elem];
    }

    __shared__ float sx[IN];      // input x[t]
    __shared__ float shh[EDIM];   // own h[t-1]

    const float* xin = layer ? (x0_trace + (size_t)s * L * EDIM)
                             : (x_in + (size_t)s * L * IN);
    float* xo = (layer ? x1_trace : x0_trace) + (size_t)s * L * EDIM;

    for (int t = 0; t < L; t++) {
        // spin phase (R7 protocol, exact)
        if (layer) {
            if (tid < NBLK) {
                const unsigned* fp = &flags0[tid];
                const unsigned tgt = base + (unsigned)t + 1u;    // x0 row t ready
                while (flag_acquire(fp) < tgt) { }
            } else if (tid < 2 * NBLK && t > 0) {
                const unsigned* fp = &flags1[tid - NBLK];
                const unsigned tgt = base + (unsigned)t;         // own row t-1 ready
                while (flag_acquire(fp) < tgt) { }
            }
        } else if (t > 0 && tid < NBLK) {
            const unsigned* fp = &flags0[tid];
            const unsigned tgt = base + (unsigned)t;
            while (flag_acquire(fp) < tgt) { }
        }
        __syncthreads();
        // stage input x (lower threads) and own h (upper threads)
        if (tid < IN / 4)
            reinterpret_cast<float4*>(sx)[tid] =
                ldcg4(reinterpret_cast<const float4*>(xin + (size_t)t * IN) + tid);
        if (tid >= 128) {
            const int i = tid - 128;
            if (t > 0)
                reinterpret_cast<float4*>(shh)[i] =
                    ldcg4(reinterpret_cast<const float4*>(xo + (size_t)(t - 1) * EDIM) + i);
            else
                reinterpret_cast<float4*>(shh)[i] = make_float4(0.f, 0.f, 0.f, 0.f);
        }
        __syncthreads();

        // matvecs (activation index kc + u*16 == weight-register index)
        float pr = 0.f, pz = 0.f, pn = 0.f;
        float qr = 0.f, qz = 0.f, qn = 0.f;
#pragma unroll
        for (int u = 0; u < 8; u++) {
            const float4 h4 = reinterpret_cast<const float4*>(shh)[kc + u * 16];
            pr += wr[u].x * h4.x; pr += wr[u].y * h4.y; pr += wr[u].z * h4.z; pr += wr[u].w * h4.w;
            pz += wz[u].x * h4.x; pz += wz[u].y * h4.y; pz += wz[u].z * h4.z; pz += wz[u].w * h4.w;
            pn += wn[u].x * h4.x; pn += wn[u].y * h4.y; pn += wn[u].z * h4.z; pn += wn[u].w * h4.w;
        }
#pragma unroll
        for (int u = 0; u < INF4; u++) {
            const float4 x4 = reinterpret_cast<const float4*>(sx)[kc + u * 16];
            qr += ur[u].x * x4.x; qr += ur[u].y * x4.y; qr += ur[u].z * x4.z; qr += ur[u].w * x4.w;
            qz += uz[u].x * x4.x; qz += uz[u].y * x4.y; qz += uz[u].z * x4.z; qz += uz[u].w * x4.w;
            qn += un[u].x * x4.x; qn += un[u].y * x4.y; qn += un[u].z * x4.z; qn += un[u].w * x4.w;
        }
        // reductions over the 16-lane group
        float sr = pr + qr, sz = pz + qz;
#pragma unroll
        for (int off = 8; off > 0; off >>= 1) {
            sr += __shfl_down_sync(0xffffffffu, sr, off, 16);
            sz += __shfl_down_sync(0xffffffffu, sz, off, 16);
            pn += __shfl_down_sync(0xffffffffu, pn, off, 16);
            qn += __shfl_down_sync(0xffffffffu, qn, off, 16);
        }
        if (kc == 0) {
            const float hold = shh[elem];
            const float r = sigf(qr + bir + sr - qr + bhr);   // == sig(sr + bir + bhr)
            const float z = sigf(sz + biz + bhz);
            const float n = tanhf(qn + bin + r * (pn + bhn));
            const float hnew = (1.f - z) * n + z * hold;
            __stcg(xo + (size_t)t * EDIM + elem, hnew);
            if (t == L - 1) hT[s * hTs + layer * EDIM + elem] = hnew;
        }
        __syncthreads();
        if (tid == 0) flag_release(myflag, base + (unsigned)t + 1u);
    }
}

// ---------------- conv1d(stride2,pad255) + bias + global maxpool ----------------
__global__ void conv_pool_kernel(float* __restrict__ seq, const float* __restrict__ hin,
                                 const float* __restrict__ cw, const float* __restrict__ cb) {
    const int s = blockIdx.x >> 1, oc = blockIdx.x & 1;
    __shared__ float sin[2 * EDIM];
    __shared__ float sw[2 * EDIM];
    __shared__ float red[256];
    const int tid = threadIdx.x;
    for (int i = tid; i < 2 * EDIM; i += 256) {
        sin[i] = hin[(size_t)s * 2 * EDIM + i];
        sw[i]  = cw[(size_t)oc * 2 * EDIM + i];
    }
    __syncthreads();
    float v = cb[oc];
    const int base = 2 * tid - 255;
    const int k0 = (base < 0) ? -base : 0;
    const int k1 = EDIM - ((base > 0) ? base : 0);
#pragma unroll 4
    for (int k = k0; k < k1; k++) {
        const int pos = base + k;
        v += sw[k] * sin[pos] + sw[EDIM + k] * sin[EDIM + pos];
    }
    red[tid] = v;
    __syncthreads();
    for (int off = 128; off > 0; off >>= 1) {
        if (tid < off) red[tid] = fmaxf(red[tid], red[tid + off]);
        __syncthreads();
    }
    const float M = red[0];
    if (tid < POOL) seq[((size_t)s * 2 + oc) * POOL + tid] = M;
}

// ---------------- head ----------------
__global__ void head_kernel(float* __restrict__ out, const float* __restrict__ hT2,
                            const float* __restrict__ WA, const float* __restrict__ WB,
                            const float* __restrict__ b_bi, const float* __restrict__ Wlin,
                            const float* __restrict__ blin) {
    const int j = threadIdx.x;
    __shared__ float shx[EDIM];
    __shared__ float shv[EDIM];
    __shared__ float red[256];
    for (int k = j; k < EDIM; k += 256) {
        const float a = hT2[k], b = hT2[EDIM + k];
        shx[k] = a * b;
        shv[k] = fabsf(a - b);
    }
    __syncthreads();
    float acc = b_bi[j];
    for (int k = 0; k < EDIM; k++)
        acc += shx[k] * WA[(size_t)k * 256 + j] + shv[k] * WB[(size_t)k * 256 + j];
    const float ht = tanhf(acc);
    red[j] = ht * Wlin[j];
    __syncthreads();
    for (int off = 128; off > 0; off >>= 1) {
        if (j < off) red[j] += red[j + off];
        __syncthreads();
    }
    if (j == 0) out[0] = 1.f / (1.f + __expf(-(red[0] + blin[0])));
}

// ---------------- launch ----------------
extern "C" void kernel_launch(void* const* d_in, const int* in_sizes, int n_in,
                              void* d_out, int out_size) {
    const int*   sentA  = (const int*)  d_in[0];
    const int*   sentB  = (const int*)  d_in[1];
    const float* emb    = (const float*)d_in[2];
    const float* Wih1   = (const float*)d_in[3];
    const float* Whh1   = (const float*)d_in[4];
    const float* bih1   = (const float*)d_in[5];
    const float* bhh1   = (const float*)d_in[6];
    const float* conv_w = (const float*)d_in[7];
    const float* conv_b = (const float*)d_in[8];
    const float* Wih2   = (const float*)d_in[9];
    const float* Whh2   = (const float*)d_in[10];
    const float* bih2   = (const float*)d_in[11];
    const float* bhh2   = (const float*)d_in[12];
    const float* WA     = (const float*)d_in[13];
    const float* WB     = (const float*)d_in[14];
    const float* b_bi   = (const float*)d_in[15];
    const float* W_lin  = (const float*)d_in[16];
    const float* b_lin  = (const float*)d_in[17];
    float* out = (float*)d_out;

    float* S = nullptr;
    cudaGetSymbolAddress((void**)&S, d_scratch);

    float* xA   = S + OFF_XA;
    float* xB   = S + OFF_XB;
    float* xC   = S + OFF_XC;
    float* fin  = S + OFF_FIN;
    float* x2a  = S + OFF_X2A;
    float* x2b  = S + OFF_X2B;
    float* x2c  = S + OFF_X2C;
    float* fin2 = S + OFF_FIN2;
    float* seq  = S + OFF_SEQ;
    float* hT2  = S + OFF_HT2;

    const size_t WSTRIDE = (size_t)JDIM * EDIM;

    // embedding (zeroes flags each replay)
    embed_kernel<<<dim3(TLEN, 2), 128>>>(xA, sentA, sentB, emb);

    // ---- epoch 0: pipelined 2-layer scan, both layers fly ----
    fused_scan_kernel<8><<<dim3(NBLK, 2, 2), 256>>>(
        xB, xC, fin, 2 * EDIM,
        xA,
        Wih1, bih1, Whh1, bhh1,
        Wih1 + WSTRIDE, bih1 + JDIM, Whh1 + WSTRIDE, bhh1 + JDIM,
        TLEN, 0u);

    // ---- epoch 1 (L = 2): both layers fly from fin ----
    fused_scan_kernel<8><<<dim3(NBLK, 2, 2), 256>>>(
        x2a, x2b, fin2, 2 * EDIM,
        fin,
        Wih1, bih1, Whh1, bhh1,
        Wih1 + WSTRIDE, bih1 + JDIM, Whh1 + WSTRIDE, bhh1 + JDIM,
        2, (unsigned)TLEN);

    // conv + pool
    conv_pool_kernel<<<4, 256>>>(seq, fin2, conv_w, conv_b);

    // rnn_second (single layer, L = 2, input dim 128, gates on the fly)
    fused_scan_kernel<2><<<dim3(NBLK, 2, 1), 256>>>(
        x2c, x2c, hT2, EDIM,
        seq,
        Wih2, bih2, Whh2, bhh2,
        Wih2, bih2, Whh2, bhh2,
        2, (unsigned)TLEN + 2u);

    // head
    head_kernel<<<1, 256>>>(out, hT2, WA, WB, b_bi, W_lin, b_lin);
}